// round 1
// baseline (speedup 1.0000x reference)
#include <cuda_runtime.h>

#define EPSF 1e-6f

// ---------------- scratch (static __device__, no allocs) ----------------
__device__ float  g_col_rl[16384];
__device__ float  g_col_ul[16384];
__device__ float  g_nl[16384];
__device__ float  g_nar[8192];
__device__ float  g_nau[8192];
__device__ double g_edge_sum;

// ---------------- fast math helpers ----------------
__device__ __forceinline__ float rsqrt_approx(float x) {
    float r;
    asm("rsqrt.approx.f32 %0, %1;" : "=f"(r) : "f"(x));
    return r;
}

// exp(y) on the FMA pipe (no MUFU): 2^t split with round-to-nearest magic
// constant, degree-5 Taylor on f*ln2, |f|<=0.5 -> rel err ~3e-6.
__device__ __forceinline__ float fast_exp(float y) {
    y = fmaxf(y, -87.0f);
    const float L2E = 1.4426950408889634f;
    float t = y * L2E;
    float z = t + 12582912.0f;                  // 1.5*2^23: round t to nearest int
    int   nb = __float_as_int(z);               // 0x4B400000 + n
    float f = t - (z - 12582912.0f);            // f in [-0.5, 0.5]
    float s = __int_as_float((nb - 0x4B400000 + 127) << 23);  // 2^n
    float g = f * 0.6931471805599453f;
    float p = 8.3333337e-3f;                    // 1/120
    p = fmaf(p, g, 4.1666668e-2f);              // 1/24
    p = fmaf(p, g, 1.6666667e-1f);              // 1/6
    p = fmaf(p, g, 0.5f);
    p = fmaf(p, g, 1.0f);
    p = fmaf(p, g, 1.0f);
    return s * p;
}

// ---------------- init: zero accumulators ----------------
__global__ void init_kernel() {
    int t = blockIdx.x * blockDim.x + threadIdx.x;
    if (t < 16384) { g_col_rl[t] = 0.0f; g_col_ul[t] = 0.0f; }
    if (t == 0) g_edge_sum = 0.0;
}

// ---------------- row norms: warp per row, D=128 ----------------
__global__ void norms_kernel(const float* __restrict__ l,
                             const float* __restrict__ r,
                             const float* __restrict__ u,
                             int I, int J, int K, int D) {
    int warp = (blockIdx.x * blockDim.x + threadIdx.x) >> 5;
    int lane = threadIdx.x & 31;
    int total = I + J + K;
    if (warp >= total) return;
    const float* src; float* dst; float e; int row;
    if (warp < I)          { src = l; dst = g_nl;  e = 0.0f; row = warp; }
    else if (warp < I + J) { src = r; dst = g_nar; e = EPSF; row = warp - I; }
    else                   { src = u; dst = g_nau; e = EPSF; row = warp - I - J; }
    float4 v = __ldg((const float4*)(src + (size_t)row * D) + lane);
    float a = v.x + e, b = v.y + e, c = v.z + e, d = v.w + e;
    float s = a * a + b * b + c * c + d * d;
    #pragma unroll
    for (int o = 16; o; o >>= 1) s += __shfl_xor_sync(0xffffffffu, s, o);
    if (lane == 0) dst[row] = s;
}

// ---------------- fused distance-GEMM + exp column reduce ----------------
// Computes col[i] += sum_j exp(bias[j] - (sqrt(max(na[j]+nl[i]-2*A_j.L_i,0)) + eps))
#define BM 128
#define BN 128
#define BK 16
#define SPAD 4

__global__ __launch_bounds__(256, 2)
void rate_kernel(const float* __restrict__ A,      // [Jdim, D] (r or u)
                 const float* __restrict__ L,      // [I, D]
                 const float* __restrict__ bias,   // nu or tau [Jdim]
                 int which,                        // 0 -> rl, 1 -> ul
                 int D, float aeps) {
    __shared__ float As[BK][BM + SPAD];
    __shared__ float Bs[BK][BN + SPAD];

    const float* na  = which ? g_nau    : g_nar;
    float*       col = which ? g_col_ul : g_col_rl;

    int tid = threadIdx.x;
    int tx = tid & 15;          // i direction (16)
    int ty = tid >> 4;          // j direction (16)
    int ib = blockIdx.x * BN;
    int jb = blockIdx.y * BM;

    float acc[8][8];
    #pragma unroll
    for (int m = 0; m < 8; m++)
        #pragma unroll
        for (int n = 0; n < 8; n++) acc[m][n] = 0.0f;

    const int nK = D / BK;      // 8 for D=128
    for (int kt = 0; kt < nK; ++kt) {
        #pragma unroll
        for (int t = 0; t < 2; t++) {
            int v   = tid + t * 256;     // 0..511
            int row = v >> 2;            // 0..127
            int c4  = v & 3;             // 0..3
            float4 av = __ldg((const float4*)(A + (size_t)(jb + row) * D + kt * BK + c4 * 4));
            As[c4 * 4 + 0][row] = av.x + aeps;
            As[c4 * 4 + 1][row] = av.y + aeps;
            As[c4 * 4 + 2][row] = av.z + aeps;
            As[c4 * 4 + 3][row] = av.w + aeps;
            float4 bv = __ldg((const float4*)(L + (size_t)(ib + row) * D + kt * BK + c4 * 4));
            Bs[c4 * 4 + 0][row] = bv.x;
            Bs[c4 * 4 + 1][row] = bv.y;
            Bs[c4 * 4 + 2][row] = bv.z;
            Bs[c4 * 4 + 3][row] = bv.w;
        }
        __syncthreads();
        #pragma unroll
        for (int k = 0; k < BK; k++) {
            float a[8], b[8];
            *(float4*)(a)     = *(const float4*)&As[k][ty * 8];
            *(float4*)(a + 4) = *(const float4*)&As[k][ty * 8 + 4];
            *(float4*)(b)     = *(const float4*)&Bs[k][tx * 8];
            *(float4*)(b + 4) = *(const float4*)&Bs[k][tx * 8 + 4];
            #pragma unroll
            for (int m = 0; m < 8; m++)
                #pragma unroll
                for (int n = 0; n < 8; n++)
                    acc[m][n] = fmaf(a[m], b[n], acc[m][n]);
        }
        __syncthreads();
    }

    // epilogue: exp(bias_j - sqrt(d2) - eps), reduce over j within block
    float nuj[8], naj[8], nli[8];
    #pragma unroll
    for (int m = 0; m < 8; m++) {
        int j = jb + ty * 8 + m;
        nuj[m] = __ldg(&bias[j]) - EPSF;
        naj[m] = na[j];
    }
    #pragma unroll
    for (int n = 0; n < 8; n++) nli[n] = g_nl[ib + tx * 8 + n];

    float colsum[8];
    #pragma unroll
    for (int n = 0; n < 8; n++) colsum[n] = 0.0f;

    #pragma unroll
    for (int m = 0; m < 8; m++) {
        #pragma unroll
        for (int n = 0; n < 8; n++) {
            float d2 = fmaf(-2.0f, acc[m][n], naj[m] + nli[n]);
            d2 = fmaxf(d2, 1e-12f);
            float d = d2 * rsqrt_approx(d2);        // sqrt: 1 MUFU + 1 mul
            colsum[n] += fast_exp(nuj[m] - d);       // exp: FMA pipe only
        }
    }

    // block-level reduce over the 16 ty rows (reuse As as [16][128] scratch)
    float* cp = &As[0][0];
    __syncthreads();
    #pragma unroll
    for (int n = 0; n < 8; n++) cp[ty * 128 + tx * 8 + n] = colsum[n];
    __syncthreads();
    if (tid < 128) {
        float s = 0.0f;
        #pragma unroll
        for (int t = 0; t < 16; t++) s += cp[t * 128 + tid];
        atomicAdd(&col[ib + tid], s);
    }
}

// ---------------- sampled edge term: warp per edge ----------------
__global__ void edge_kernel(const float* __restrict__ l, const float* __restrict__ r,
                            const float* __restrict__ u,
                            const float* __restrict__ rho, const float* __restrict__ nu,
                            const float* __restrict__ tau,
                            const float* __restrict__ w,
                            const int* __restrict__ si, const int* __restrict__ sj,
                            const int* __restrict__ sk, int E, int D) {
    int lane = threadIdx.x & 31;
    int warp = (blockIdx.x * blockDim.x + threadIdx.x) >> 5;
    int nwarps = (gridDim.x * blockDim.x) >> 5;
    float local = 0.0f;
    for (int e = warp; e < E; e += nwarps) {
        int i = __ldg(&si[e]);
        int j = __ldg(&sj[e]);
        int k = __ldg(&sk[e]);
        float4 lv = __ldg((const float4*)(l + (size_t)i * D) + lane);
        float4 rv = __ldg((const float4*)(r + (size_t)j * D) + lane);
        float4 uv = __ldg((const float4*)(u + (size_t)k * D) + lane);
        float ax = lv.x - rv.x + EPSF, ay = lv.y - rv.y + EPSF;
        float az = lv.z - rv.z + EPSF, aw = lv.w - rv.w + EPSF;
        float bx = lv.x - uv.x + EPSF, by = lv.y - uv.y + EPSF;
        float bz = lv.z - uv.z + EPSF, bw = lv.w - uv.w + EPSF;
        float s1 = ax * ax + ay * ay + az * az + aw * aw;
        float s2 = bx * bx + by * by + bz * bz + bw * bw;
        #pragma unroll
        for (int o = 16; o; o >>= 1) {
            s1 += __shfl_xor_sync(0xffffffffu, s1, o);
            s2 += __shfl_xor_sync(0xffffffffu, s2, o);
        }
        if (lane == 0) {
            s1 = fmaxf(s1, 1e-12f);
            s2 = fmaxf(s2, 1e-12f);
            float d1 = s1 * rsqrt_approx(s1);
            float d2 = s2 * rsqrt_approx(s2);
            local += __ldg(&w[e]) * (__ldg(&rho[i]) + __ldg(&nu[j]) + __ldg(&tau[k]) - d1 - d2);
        }
    }
    if (lane == 0) atomicAdd(&g_edge_sum, (double)local);
}

// ---------------- final scalar: z2 - sum_i col_rl * exp(rho) * col_ul ----------------
__global__ void final_kernel(const float* __restrict__ rho, float* __restrict__ out, int I) {
    __shared__ double sm[256];
    int tid = threadIdx.x;
    double s = 0.0;
    for (int i = tid; i < I; i += 256)
        s += (double)g_col_rl[i] * (double)(__expf(rho[i]) * g_col_ul[i]);
    sm[tid] = s;
    __syncthreads();
    for (int o = 128; o; o >>= 1) {
        if (tid < o) sm[tid] += sm[tid + o];
        __syncthreads();
    }
    if (tid == 0) out[0] = (float)(g_edge_sum - sm[0]);
}

// ---------------- launch ----------------
extern "C" void kernel_launch(void* const* d_in, const int* in_sizes, int n_in,
                              void* d_out, int out_size) {
    const float* l   = (const float*)d_in[0];
    const float* r   = (const float*)d_in[1];
    const float* u   = (const float*)d_in[2];
    const float* rho = (const float*)d_in[3];
    const float* nu  = (const float*)d_in[4];
    const float* tau = (const float*)d_in[5];
    const float* w   = (const float*)d_in[6];
    const int*   si  = (const int*)d_in[7];
    const int*   sj  = (const int*)d_in[8];
    const int*   sk  = (const int*)d_in[9];

    int I = in_sizes[3];
    int J = in_sizes[4];
    int K = in_sizes[5];
    int E = in_sizes[6];
    int D = in_sizes[0] / I;   // 128

    init_kernel<<<64, 256>>>();
    int rows = I + J + K;
    norms_kernel<<<(rows + 7) / 8, 256>>>(l, r, u, I, J, K, D);

    dim3 g1(I / BN, J / BM);
    rate_kernel<<<g1, 256>>>(r, l, nu, 0, D, EPSF);
    dim3 g2(I / BN, K / BM);
    rate_kernel<<<g2, 256>>>(u, l, tau, 1, D, EPSF);

    edge_kernel<<<2048, 256>>>(l, r, u, rho, nu, tau, w, si, sj, sk, E, D);
    final_kernel<<<1, 256>>>(rho, (float*)d_out, I);
}

// round 4
// speedup vs baseline: 2.6141x; 2.6141x over previous
#include <cuda_runtime.h>
#include <cuda_bf16.h>
#include <cstdint>

#define EPSF 1e-6f
#define L2E  1.4426950408889634f

static constexpr int I_DIM = 16384;
static constexpr int JK_DIM = 8192;
static constexpr int D_DIM = 128;

// ---------------- scratch (static __device__, no allocs) ----------------
__device__ __nv_bfloat16 g_lb[I_DIM * D_DIM];
__device__ __nv_bfloat16 g_rb[JK_DIM * D_DIM];
__device__ __nv_bfloat16 g_ub[JK_DIM * D_DIM];
__device__ float  g_col_rl[I_DIM];
__device__ float  g_col_ul[I_DIM];
__device__ float  g_nl[I_DIM];     // ||l||^2 - 2*eps*sum(l): folds A-side eps into GEMM
__device__ float  g_nar[JK_DIM];   // ||r+eps||^2
__device__ float  g_nau[JK_DIM];   // ||u+eps||^2
__device__ double g_edge_sum;

// ---------------- helpers ----------------
__device__ __forceinline__ uint32_t smem_u32(const void* p) {
    uint32_t a;
    asm("{ .reg .u64 t; cvta.to.shared.u64 t, %1; cvt.u32.u64 %0, t; }" : "=r"(a) : "l"(p));
    return a;
}
__device__ __forceinline__ float sqrt_approx(float x) {
    float r; asm("sqrt.approx.f32 %0, %1;" : "=f"(r) : "f"(x)); return r;
}
__device__ __forceinline__ float rsqrt_approx(float x) {
    float r; asm("rsqrt.approx.f32 %0, %1;" : "=f"(r) : "f"(x)); return r;
}
// 2^t on the FMA pipe: magic-constant round + degree-5 poly on f in [-0.5,0.5]
__device__ __forceinline__ float fast_ex2(float t) {
    t = fmaxf(t, -120.0f);
    float z = t + 12582912.0f;
    int   nb = __float_as_int(z) - 0x4B400000;
    float f = t - (z - 12582912.0f);
    float s = __int_as_float((nb + 127) << 23);
    float p = 1.3333558e-3f;
    p = fmaf(p, f, 9.6181291e-3f);
    p = fmaf(p, f, 5.5504109e-2f);
    p = fmaf(p, f, 2.4022651e-1f);
    p = fmaf(p, f, 6.9314718e-1f);
    p = fmaf(p, f, 1.0f);
    return s * p;
}
__device__ __forceinline__ float4 ld_bf16x4(const __nv_bfloat16* p) {
    uint2 v = *(const uint2*)p;
    __nv_bfloat162 lo = *(__nv_bfloat162*)&v.x;
    __nv_bfloat162 hi = *(__nv_bfloat162*)&v.y;
    float2 f0 = __bfloat1622float2(lo), f1 = __bfloat1622float2(hi);
    return make_float4(f0.x, f0.y, f1.x, f1.y);
}
__device__ __forceinline__ void ldsm_x4(uint32_t& r0, uint32_t& r1, uint32_t& r2, uint32_t& r3,
                                        uint32_t addr) {
    asm volatile("ldmatrix.sync.aligned.m8n8.x4.shared.b16 {%0,%1,%2,%3}, [%4];"
                 : "=r"(r0), "=r"(r1), "=r"(r2), "=r"(r3) : "r"(addr));
}
__device__ __forceinline__ void ldsm_x2(uint32_t& r0, uint32_t& r1, uint32_t addr) {
    asm volatile("ldmatrix.sync.aligned.m8n8.x2.shared.b16 {%0,%1}, [%2];"
                 : "=r"(r0), "=r"(r1) : "r"(addr));
}
__device__ __forceinline__ void mma_16816(float* c, const uint32_t* a, const uint32_t* b) {
    asm volatile(
        "mma.sync.aligned.m16n8k16.row.col.f32.bf16.bf16.f32 "
        "{%0,%1,%2,%3}, {%4,%5,%6,%7}, {%8,%9}, {%0,%1,%2,%3};"
        : "+f"(c[0]), "+f"(c[1]), "+f"(c[2]), "+f"(c[3])
        : "r"(a[0]), "r"(a[1]), "r"(a[2]), "r"(a[3]), "r"(b[0]), "r"(b[1]));
}

// ---------------- init ----------------
__global__ void init_kernel() {
    int t = blockIdx.x * blockDim.x + threadIdx.x;
    if (t < I_DIM) { g_col_rl[t] = 0.0f; g_col_ul[t] = 0.0f; }
    if (t == 0) g_edge_sum = 0.0;
}

// ---------------- convert fp32 -> bf16 + norms (warp per row) ----------------
__global__ void convert_kernel(const float* __restrict__ l,
                               const float* __restrict__ r,
                               const float* __restrict__ u) {
    int warp = (blockIdx.x * blockDim.x + threadIdx.x) >> 5;
    int lane = threadIdx.x & 31;
    int total = I_DIM + 2 * JK_DIM;
    if (warp >= total) return;
    const float* src; __nv_bfloat16* dstb; float* dstn; int row; bool isL;
    if (warp < I_DIM)               { src = l; dstb = g_lb; dstn = g_nl;  row = warp;                 isL = true;  }
    else if (warp < I_DIM + JK_DIM) { src = r; dstb = g_rb; dstn = g_nar; row = warp - I_DIM;          isL = false; }
    else                            { src = u; dstb = g_ub; dstn = g_nau; row = warp - I_DIM - JK_DIM; isL = false; }
    float4 v = __ldg((const float4*)(src + (size_t)row * D_DIM) + lane);
    __nv_bfloat162 b0 = __float22bfloat162_rn(make_float2(v.x, v.y));
    __nv_bfloat162 b1 = __float22bfloat162_rn(make_float2(v.z, v.w));
    uint2 pk; pk.x = *(uint32_t*)&b0; pk.y = *(uint32_t*)&b1;
    *((uint2*)(dstb + (size_t)row * D_DIM) + lane) = pk;
    float s, t;
    if (isL) {
        s = v.x * v.x + v.y * v.y + v.z * v.z + v.w * v.w;
        t = v.x + v.y + v.z + v.w;
    } else {
        float a = v.x + EPSF, b = v.y + EPSF, c = v.z + EPSF, d = v.w + EPSF;
        s = a * a + b * b + c * c + d * d;
        t = 0.0f;
    }
    #pragma unroll
    for (int o = 16; o; o >>= 1) {
        s += __shfl_xor_sync(0xffffffffu, s, o);
        t += __shfl_xor_sync(0xffffffffu, t, o);
    }
    if (lane == 0) dstn[row] = isL ? (s - 2.0f * EPSF * t) : s;
}

// ---------------- rate term: bf16 HMMA GEMM + fused exp epilogue ----------------
// Block tile: 128 j-rows x 128 i-cols, K=128 resident. 8 warps as 4(j) x 2(i),
// warp tile 32x64 via m16n8k16. col[i] += sum_j exp(bias_j - eps - sqrt(d2)).
// SMEM tiles: row = 256B (128 bf16), XOR swizzle on 16B chunks: chunk ^ (row&7).
#define TILE_ROW_B 256
#define A_OFF 0
#define B_OFF (128 * TILE_ROW_B)            // 32768
#define EP_STRIDE 132                        // floats
#define RATE_SMEM 69632                      // >= max(2*32KB tiles, 128*132*4 ep)

__global__ __launch_bounds__(256, 2)
void rate_tc_kernel(const float* __restrict__ bias, int which) {
    extern __shared__ char dsmem[];
    __shared__ float nl_s[128];

    const __nv_bfloat16* Ab = which ? g_ub : g_rb;
    const float* na  = which ? g_nau : g_nar;
    float*       col = which ? g_col_ul : g_col_rl;

    int tid = threadIdx.x;
    int wid = tid >> 5;
    int lane = tid & 31;
    int wj = wid >> 1;          // 0..3 -> j offset wj*32
    int wi = wid & 1;           // 0..1 -> i offset wi*64
    int ib = blockIdx.x * 128;
    int jb = blockIdx.y * 128;

    uint32_t sb = smem_u32(dsmem);

    // ---- load tiles: each tile 128 rows x 16 chunks(16B), 2048 uint4 total ----
    #pragma unroll
    for (int t = 0; t < 8; t++) {
        int idx = tid + t * 256;
        int row = idx >> 4, c = idx & 15;
        int sc = c ^ (row & 7);
        uint4 va = __ldg((const uint4*)(Ab + (size_t)(jb + row) * D_DIM) + c);
        *(uint4*)(dsmem + A_OFF + row * TILE_ROW_B + sc * 16) = va;
        uint4 vb = __ldg((const uint4*)(g_lb + (size_t)(ib + row) * D_DIM) + c);
        *(uint4*)(dsmem + B_OFF + row * TILE_ROW_B + sc * 16) = vb;
    }
    if (tid < 128) nl_s[tid] = g_nl[ib + tid];
    __syncthreads();

    // ---- mainloop: 8 k-steps of m16n8k16 ----
    float acc[2][8][4];
    #pragma unroll
    for (int mt = 0; mt < 2; mt++)
        #pragma unroll
        for (int nt = 0; nt < 8; nt++)
            #pragma unroll
            for (int e = 0; e < 4; e++) acc[mt][nt][e] = 0.0f;

    // A ldmatrix address pieces: row = wj*32 + mt*16 + (lane&15), chunk = ks*2 + (lane>>4)
    int a_row0 = wj * 32 + (lane & 15);
    int a_csel = lane >> 4;              // 0/1
    // B: row = wi*64 + nt*8 + (lane&7), chunk = ks*2 + ((lane>>3)&1)
    int b_row0 = wi * 64 + (lane & 7);
    int b_csel = (lane >> 3) & 1;

    #pragma unroll
    for (int ks = 0; ks < 8; ks++) {
        uint32_t a[2][4];
        #pragma unroll
        for (int mt = 0; mt < 2; mt++) {
            int row = a_row0 + mt * 16;
            int c = (ks * 2 + a_csel) ^ (row & 7);
            ldsm_x4(a[mt][0], a[mt][1], a[mt][2], a[mt][3],
                    sb + A_OFF + row * TILE_ROW_B + c * 16);
        }
        uint32_t b[8][2];
        #pragma unroll
        for (int nt = 0; nt < 8; nt++) {
            int row = b_row0 + nt * 8;
            int c = (ks * 2 + b_csel) ^ (row & 7);
            ldsm_x2(b[nt][0], b[nt][1], sb + B_OFF + row * TILE_ROW_B + c * 16);
        }
        #pragma unroll
        for (int mt = 0; mt < 2; mt++)
            #pragma unroll
            for (int nt = 0; nt < 8; nt++)
                mma_16816(acc[mt][nt], a[mt], b[nt]);
    }

    __syncthreads();   // tiles no longer needed; reuse smem as ep[128][132] floats

    // ---- epilogue: exp(bias_j - eps - sqrt(d2)) staged to smem ----
    float* ep = (float*)dsmem;
    int g = lane >> 2;                 // row group
    int tq = lane & 3;                 // col quad
    float c1j[4], c0j[4];
    #pragma unroll
    for (int mt = 0; mt < 2; mt++)
        #pragma unroll
        for (int h = 0; h < 2; h++) {
            int jr = wj * 32 + mt * 16 + g + h * 8;
            c1j[mt * 2 + h] = na[jb + jr];
            c0j[mt * 2 + h] = (__ldg(&bias[jb + jr]) - EPSF) * L2E;
        }

    #pragma unroll
    for (int mt = 0; mt < 2; mt++) {
        #pragma unroll
        for (int nt = 0; nt < 8; nt++) {
            int i0 = wi * 64 + nt * 8 + tq * 2;
            float n0 = nl_s[i0], n1 = nl_s[i0 + 1];
            #pragma unroll
            for (int h = 0; h < 2; h++) {
                int jr = wj * 32 + mt * 16 + g + h * 8;
                float na_j = c1j[mt * 2 + h], b_j = c0j[mt * 2 + h];
                float d20 = fmaf(-2.0f, acc[mt][nt][h * 2 + 0], na_j + n0);
                float d21 = fmaf(-2.0f, acc[mt][nt][h * 2 + 1], na_j + n1);
                d20 = fmaxf(d20, 0.0f);
                d21 = fmaxf(d21, 0.0f);
                float v0 = fast_ex2(fmaf(sqrt_approx(d20), -L2E, b_j));
                float v1 = fast_ex2(fmaf(sqrt_approx(d21), -L2E, b_j));
                *(float2*)&ep[jr * EP_STRIDE + i0] = make_float2(v0, v1);
            }
        }
    }
    __syncthreads();

    // ---- reduce over j (128) per i-column; 2 partials per column ----
    {
        int ci = tid & 127;
        int half = tid >> 7;
        float s = 0.0f;
        #pragma unroll
        for (int j = 0; j < 64; j++)
            s += ep[(half * 64 + j) * EP_STRIDE + ci];
        atomicAdd(&col[ib + ci], s);
    }
}

// ---------------- sampled edge term: warp per edge, bf16 gathers ----------------
__global__ void edge_kernel(const float* __restrict__ rho, const float* __restrict__ nu,
                            const float* __restrict__ tau, const float* __restrict__ w,
                            const int* __restrict__ si, const int* __restrict__ sj,
                            const int* __restrict__ sk, int E) {
    int lane = threadIdx.x & 31;
    int warp = (blockIdx.x * blockDim.x + threadIdx.x) >> 5;
    int nwarps = (gridDim.x * blockDim.x) >> 5;
    float local = 0.0f;
    for (int e = warp; e < E; e += nwarps) {
        int i = __ldg(&si[e]);
        int j = __ldg(&sj[e]);
        int k = __ldg(&sk[e]);
        float4 lv = ld_bf16x4(g_lb + (size_t)i * D_DIM + lane * 4);
        float4 rv = ld_bf16x4(g_rb + (size_t)j * D_DIM + lane * 4);
        float4 uv = ld_bf16x4(g_ub + (size_t)k * D_DIM + lane * 4);
        float ax = lv.x - rv.x + EPSF, ay = lv.y - rv.y + EPSF;
        float az = lv.z - rv.z + EPSF, aw = lv.w - rv.w + EPSF;
        float bx = lv.x - uv.x + EPSF, by = lv.y - uv.y + EPSF;
        float bz = lv.z - uv.z + EPSF, bw = lv.w - uv.w + EPSF;
        float s1 = ax * ax + ay * ay + az * az + aw * aw;
        float s2 = bx * bx + by * by + bz * bz + bw * bw;
        #pragma unroll
        for (int o = 16; o; o >>= 1) {
            s1 += __shfl_xor_sync(0xffffffffu, s1, o);
            s2 += __shfl_xor_sync(0xffffffffu, s2, o);
        }
        if (lane == 0) {
            s1 = fmaxf(s1, 1e-12f);
            s2 = fmaxf(s2, 1e-12f);
            float d1 = s1 * rsqrt_approx(s1);
            float d2 = s2 * rsqrt_approx(s2);
            local += __ldg(&w[e]) * (__ldg(&rho[i]) + __ldg(&nu[j]) + __ldg(&tau[k]) - d1 - d2);
        }
    }
    if (lane == 0) atomicAdd(&g_edge_sum, (double)local);
}

// ---------------- final scalar ----------------
__global__ void final_kernel(const float* __restrict__ rho, float* __restrict__ out) {
    __shared__ double sm[256];
    int tid = threadIdx.x;
    double s = 0.0;
    for (int i = tid; i < I_DIM; i += 256)
        s += (double)g_col_rl[i] * (double)(__expf(rho[i]) * g_col_ul[i]);
    sm[tid] = s;
    __syncthreads();
    for (int o = 128; o; o >>= 1) {
        if (tid < o) sm[tid] += sm[tid + o];
        __syncthreads();
    }
    if (tid == 0) out[0] = (float)(g_edge_sum - sm[0]);
}

// ---------------- launch ----------------
extern "C" void kernel_launch(void* const* d_in, const int* in_sizes, int n_in,
                              void* d_out, int out_size) {
    const float* l   = (const float*)d_in[0];
    const float* r   = (const float*)d_in[1];
    const float* u   = (const float*)d_in[2];
    const float* rho = (const float*)d_in[3];
    const float* nu  = (const float*)d_in[4];
    const float* tau = (const float*)d_in[5];
    const float* w   = (const float*)d_in[6];
    const int*   si  = (const int*)d_in[7];
    const int*   sj  = (const int*)d_in[8];
    const int*   sk  = (const int*)d_in[9];
    int E = in_sizes[6];

    cudaFuncSetAttribute(rate_tc_kernel, cudaFuncAttributeMaxDynamicSharedMemorySize, RATE_SMEM);

    init_kernel<<<64, 256>>>();
    int rows = I_DIM + 2 * JK_DIM;
    convert_kernel<<<(rows + 7) / 8, 256>>>(l, r, u);

    dim3 g(I_DIM / 128, JK_DIM / 128);
    rate_tc_kernel<<<g, 256, RATE_SMEM>>>(nu, 0);
    rate_tc_kernel<<<g, 256, RATE_SMEM>>>(tau, 1);

    edge_kernel<<<2048, 256>>>(rho, nu, tau, w, si, sj, sk, E);
    final_kernel<<<1, 256>>>(rho, (float*)d_out);
}